// round 1
// baseline (speedup 1.0000x reference)
#include <cuda_runtime.h>

// ============================================================================
// TorusConv3D via FFT diagonalization.
//   out[b,s,f] = sum_{t,c} in[b, (s-t) mod 8 (per axis), c] * ker[t,f,c] + bias[f]
// => Yhat[b,k,f] = sum_c Xhat[b,k,c] * What[k,f,c]   (plain complex product)
//    out = (1/512) * Re(IFFT3(Yhat)) + bias
// All fp32. Shapes: B=64, S=8^3=512 spatial, C=64, F=64.
// ============================================================================

#define R2 0.70710678118654752440f

// Scratch (module-load-time global allocations; no runtime malloc).
// Layouts chosen for the pointwise GEMM stage:
//   g_Xhat[k*4096 + b*64 + c], g_What[k*4096 + f*64 + c], g_Yhat[k*4096 + b*64 + f]
__device__ float2 g_Xhat[512 * 64 * 64];
__device__ float2 g_What[512 * 64 * 64];
__device__ float2 g_Yhat[512 * 64 * 64];

// ---------------------------------------------------------------------------
// Dense 8-point DFT. Fully unrolled; twiddles fold to immediates (many are
// 0 / +-1 / +-sqrt(2)/2, so ptxas prunes most multiplies).
// Forward: e^{-2*pi*i*n/8}.  INV=1 conjugates (inverse, unscaled).
// ---------------------------------------------------------------------------
template <int INV>
__device__ __forceinline__ void dft8(const float2* v, float2* o) {
    const float twre[8] = {1.f, R2, 0.f, -R2, -1.f, -R2, 0.f, R2};
    const float twim[8] = {0.f, -R2, -1.f, -R2, 0.f, R2, 1.f, R2};
#pragma unroll
    for (int k = 0; k < 8; ++k) {
        float re = 0.f, im = 0.f;
#pragma unroll
        for (int x = 0; x < 8; ++x) {
            const int n = (k * x) & 7;
            const float tr = twre[n];
            const float ti = INV ? -twim[n] : twim[n];
            re += v[x].x * tr - v[x].y * ti;
            im += v[x].x * ti + v[x].y * tr;
        }
        o[k].x = re;
        o[k].y = im;
    }
}

template <int INV>
__device__ __forceinline__ void line_pass(float2* V, int base0, int stride) {
    float2 buf[8], o[8];
#pragma unroll
    for (int n = 0; n < 8; ++n) buf[n] = V[base0 + n * stride];
    dft8<INV>(buf, o);
#pragma unroll
    for (int n = 0; n < 8; ++n) V[base0 + n * stride] = o[n];
}

// 3D FFT over an smem volume V[s*32 + c], s = x*64 + y*8 + z, c in [0,32).
// c is the fastest smem index everywhere -> conflict-free LDS/STS.64.
template <int INV, int NT>
__device__ __forceinline__ void fft3d_passes(float2* V) {
    const int tid = threadIdx.x;
    // x-axis: stride 64*32 = 2048
    for (int l = tid; l < 2048; l += NT) {
        const int c = l & 31, r = l >> 5;  // r = y*8+z
        line_pass<INV>(V, r * 32 + c, 2048);
    }
    __syncthreads();
    // y-axis: stride 8*32 = 256
    for (int l = tid; l < 2048; l += NT) {
        const int c = l & 31, t = l >> 5, x = t >> 3, z = t & 7;
        line_pass<INV>(V, x * 2048 + z * 32 + c, 256);
    }
    __syncthreads();
    // z-axis: stride 32
    for (int l = tid; l < 2048; l += NT) {
        const int c = l & 31, t = l >> 5, x = t >> 3, y = t & 7;
        line_pass<INV>(V, x * 2048 + y * 256 + c, 32);
    }
    __syncthreads();
}

// ---------------------------------------------------------------------------
// Forward FFT of a real tensor. One CTA handles one "row" (batch b or filter f)
// and a 32-wide channel half. Generic strides cover both layouts:
//   inputs[b,s,c]  : rowStride = 512*64, sStride = 64
//   kernel[t,f,c]  : rowStride = 64,     sStride = 64*64
// Output: out[k*4096 + row*64 + c0 + c].
// ---------------------------------------------------------------------------
__global__ void fft3d_fwd_kernel(const float* __restrict__ in, float2* __restrict__ out,
                                 long rowStride, long sStride) {
    extern __shared__ float2 V[];  // 512 x 32 complex = 128 KB
    const int row = blockIdx.x >> 1;
    const int c0 = (blockIdx.x & 1) * 32;
    const int tid = threadIdx.x;

    const float* base = in + (long)row * rowStride + c0;
    for (int i = tid; i < 16384; i += 512) {
        const int s = i >> 5, c = i & 31;
        V[i] = make_float2(base[(long)s * sStride + c], 0.f);
    }
    __syncthreads();

    fft3d_passes<0, 512>(V);

    for (int i = tid; i < 16384; i += 512) {
        const int s = i >> 5, c = i & 31;
        out[(long)s * 4096 + row * 64 + c0 + c] = V[i];
    }
}

// ---------------------------------------------------------------------------
// Pointwise batched complex GEMM: one CTA per frequency k.
//   Y[b,f] = sum_c A[b,c] * B[f,c]   (complex, no conjugate)
// smem stored transposed + padded ([c][row], stride 65) so the inner-loop
// LDS are broadcast (A) / unit-stride (B). Strided 4x4 register tiles.
// ---------------------------------------------------------------------------
__global__ void pointwise_kernel(const float2* __restrict__ Xh, const float2* __restrict__ Wh,
                                 float2* __restrict__ Yh) {
    extern __shared__ float2 sm[];
    float2* As = sm;             // [c][b], stride 65
    float2* Bs = sm + 64 * 65;   // [c][f], stride 65
    const int k = blockIdx.x;
    const int tid = threadIdx.x;  // 256

    const float2* xk = Xh + (long)k * 4096;
    const float2* wk = Wh + (long)k * 4096;
    for (int i = tid; i < 4096; i += 256) {
        const int rowi = i >> 6, c = i & 63;
        As[c * 65 + rowi] = xk[i];
        Bs[c * 65 + rowi] = wk[i];
    }
    __syncthreads();

    const int ft = tid & 15;   // f in {ft, ft+16, ft+32, ft+48}
    const int bt = tid >> 4;   // b in {bt, bt+16, bt+32, bt+48}
    float accx[4][4] = {}, accy[4][4] = {};
    float ax[4], ay[4], bx[4], by[4];

#pragma unroll 2
    for (int c = 0; c < 64; ++c) {
#pragma unroll
        for (int i = 0; i < 4; ++i) {
            const float2 t = As[c * 65 + bt + 16 * i];
            ax[i] = t.x; ay[i] = t.y;
        }
#pragma unroll
        for (int j = 0; j < 4; ++j) {
            const float2 t = Bs[c * 65 + ft + 16 * j];
            bx[j] = t.x; by[j] = t.y;
        }
#pragma unroll
        for (int i = 0; i < 4; ++i)
#pragma unroll
            for (int j = 0; j < 4; ++j) {
                accx[i][j] += ax[i] * bx[j] - ay[i] * by[j];
                accy[i][j] += ax[i] * by[j] + ay[i] * bx[j];
            }
    }

    float2* yk = Yh + (long)k * 4096;
#pragma unroll
    for (int i = 0; i < 4; ++i)
#pragma unroll
        for (int j = 0; j < 4; ++j)
            yk[(bt + 16 * i) * 64 + ft + 16 * j] = make_float2(accx[i][j], accy[i][j]);
}

// ---------------------------------------------------------------------------
// Inverse FFT of Yhat, take real part, scale 1/512, add bias, write output.
// One CTA per (batch b, 32-wide f half).
// ---------------------------------------------------------------------------
__global__ void ifft3d_kernel(const float2* __restrict__ Yh, const float* __restrict__ bias,
                              float* __restrict__ out) {
    extern __shared__ float2 V[];  // 512 x 32 complex
    const int b = blockIdx.x >> 1;
    const int f0 = (blockIdx.x & 1) * 32;
    const int tid = threadIdx.x;

    for (int i = tid; i < 16384; i += 512) {
        const int s = i >> 5, f = i & 31;
        V[i] = Yh[(long)s * 4096 + b * 64 + f0 + f];
    }
    __syncthreads();

    fft3d_passes<1, 512>(V);

    for (int i = tid; i < 16384; i += 512) {
        const int s = i >> 5, f = i & 31;
        out[((long)(b * 512 + s)) * 64 + f0 + f] = V[i].x * (1.f / 512.f) + bias[f0 + f];
    }
}

// ---------------------------------------------------------------------------
// Launch: 4 kernels, all graph-capturable (no allocs, no syncs, no memcpy).
// ---------------------------------------------------------------------------
extern "C" void kernel_launch(void* const* d_in, const int* in_sizes, int n_in,
                              void* d_out, int out_size) {
    const float* inputs = (const float*)d_in[0];  // (64, 8,8,8, 64)
    const float* kern   = (const float*)d_in[1];  // (8,8,8, 64, 64)
    const float* bias   = (const float*)d_in[2];  // (64,)
    float* out = (float*)d_out;                   // (64, 8,8,8, 64)

    float2 *Xh, *Wh, *Yh;
    cudaGetSymbolAddress((void**)&Xh, g_Xhat);
    cudaGetSymbolAddress((void**)&Wh, g_What);
    cudaGetSymbolAddress((void**)&Yh, g_Yhat);

    const int smemFFT = 512 * 32 * (int)sizeof(float2);    // 131072 B
    const int smemPW  = 2 * 64 * 65 * (int)sizeof(float2); // 66560 B
    cudaFuncSetAttribute(fft3d_fwd_kernel, cudaFuncAttributeMaxDynamicSharedMemorySize, smemFFT);
    cudaFuncSetAttribute(ifft3d_kernel,    cudaFuncAttributeMaxDynamicSharedMemorySize, smemFFT);
    cudaFuncSetAttribute(pointwise_kernel, cudaFuncAttributeMaxDynamicSharedMemorySize, smemPW);

    // X^ = FFT3(inputs): row = b, rowStride = 512*64, sStride = 64
    fft3d_fwd_kernel<<<128, 512, smemFFT>>>(inputs, Xh, 32768L, 64L);
    // W^ = FFT3(kernel): row = f, rowStride = 64, sStride = 64*64
    fft3d_fwd_kernel<<<128, 512, smemFFT>>>(kern, Wh, 64L, 4096L);
    // Y^[b,k,f] = sum_c X^[b,k,c] * W^[k,f,c]
    pointwise_kernel<<<512, 256, smemPW>>>(Xh, Wh, Yh);
    // out = Re(IFFT3(Y^))/512 + bias
    ifft3d_kernel<<<128, 512, smemFFT>>>(Yh, bias, out);
}

// round 2
// speedup vs baseline: 1.3035x; 1.3035x over previous
#include <cuda_runtime.h>

// ============================================================================
// TorusConv3D via FFT diagonalization (round 2).
//   out[b,s,f] = sum_{t,c} in[b, s-t mod 8, c] * ker[t,f,c] + bias[f]
// => Yhat[b,k,f] = sum_c Xhat[b,k,c] * What[k,f,c];  out = Re(IFFT3(Yhat))/512 + bias
// Round-2 changes: radix-2 FFT8, 16-channel FFT tiles (3 CTAs/SM), Hermitian
// pointwise (260 canonical freqs, conjugate partner written directly),
// float4-vectorized global I/O, fused forward FFTs.
// ============================================================================

#define R2 0.70710678118654752440f

// Layouts: g_Xhat[k*4096 + b*64 + c], g_What[k*4096 + f*64 + c], g_Yhat[k*4096 + b*64 + f]
__device__ float2 g_Xhat[512 * 64 * 64];
__device__ float2 g_What[512 * 64 * 64];
__device__ float2 g_Yhat[512 * 64 * 64];

// ---------------------------------------------------------------------------
// Radix-2 DIT 8-point FFT, in place. Forward = e^{-2pi i nk/8}; INV conjugates.
// ---------------------------------------------------------------------------
__device__ __forceinline__ float2 cadd(float2 a, float2 b) { return make_float2(a.x + b.x, a.y + b.y); }
__device__ __forceinline__ float2 csub(float2 a, float2 b) { return make_float2(a.x - b.x, a.y - b.y); }
template <int INV>
__device__ __forceinline__ float2 mulmi(float2 a) {  // *(-i) fwd, *(+i) inv
    return INV ? make_float2(-a.y, a.x) : make_float2(a.y, -a.x);
}
template <int INV>
__device__ __forceinline__ float2 mulw1(float2 a) {  // *W8^1 fwd, *conj inv
    return INV ? make_float2(R2 * (a.x - a.y), R2 * (a.y + a.x))
               : make_float2(R2 * (a.x + a.y), R2 * (a.y - a.x));
}
template <int INV>
__device__ __forceinline__ float2 mulw3(float2 a) {  // *W8^3 fwd, *conj inv
    return INV ? make_float2(R2 * (-a.x - a.y), R2 * (a.x - a.y))
               : make_float2(R2 * (a.y - a.x), R2 * (-a.x - a.y));
}

template <int INV>
__device__ __forceinline__ void fft8(float2* v) {
    float2 t0 = cadd(v[0], v[4]), t1 = csub(v[0], v[4]);
    float2 t2 = cadd(v[2], v[6]), t3 = csub(v[2], v[6]);
    float2 t4 = cadd(v[1], v[5]), t5 = csub(v[1], v[5]);
    float2 t6 = cadd(v[3], v[7]), t7 = csub(v[3], v[7]);
    float2 a0 = cadd(t0, t2), a1 = csub(t0, t2);
    float2 m3 = mulmi<INV>(t3);
    float2 a2 = cadd(t1, m3), a3 = csub(t1, m3);
    float2 b0 = cadd(t4, t6), b1 = csub(t4, t6);
    float2 m7 = mulmi<INV>(t7);
    float2 b2 = cadd(t5, m7), b3 = csub(t5, m7);
    float2 mb1 = mulmi<INV>(b1);
    float2 w1 = mulw1<INV>(b2);
    float2 w3 = mulw3<INV>(b3);
    v[0] = cadd(a0, b0); v[4] = csub(a0, b0);
    v[2] = cadd(a1, mb1); v[6] = csub(a1, mb1);
    v[1] = cadd(a2, w1); v[5] = csub(a2, w1);
    v[3] = cadd(a3, w3); v[7] = csub(a3, w3);
}

template <int INV>
__device__ __forceinline__ void line_pass(float2* V, int base0, int stride) {
    float2 buf[8];
#pragma unroll
    for (int n = 0; n < 8; ++n) buf[n] = V[base0 + n * stride];
    fft8<INV>(buf);
#pragma unroll
    for (int n = 0; n < 8; ++n) V[base0 + n * stride] = buf[n];
}

// 3D FFT over smem volume V[s*16 + c], s = x*64+y*8+z, c in [0,16). 256 threads.
// Strides (elems): x=1024, y=128, z=16. All passes conflict-free (c fast).
template <int INV>
__device__ __forceinline__ void fft3d_passes16(float2* V) {
    const int tid = threadIdx.x;
    const int c = tid & 15;
#pragma unroll
    for (int m = 0; m < 4; ++m) {  // x-axis
        const int r = (tid >> 4) + m * 16;  // r = y*8+z, 0..63
        line_pass<INV>(V, r * 16 + c, 1024);
    }
    __syncthreads();
#pragma unroll
    for (int m = 0; m < 4; ++m) {  // y-axis
        const int t = (tid >> 4) + m * 16;  // (x,z)
        line_pass<INV>(V, (t >> 3) * 1024 + (t & 7) * 16 + c, 128);
    }
    __syncthreads();
#pragma unroll
    for (int m = 0; m < 4; ++m) {  // z-axis
        const int t = (tid >> 4) + m * 16;  // (x,y)
        line_pass<INV>(V, (t >> 3) * 1024 + (t & 7) * 128 + c, 16);
    }
    __syncthreads();
}

// ---------------------------------------------------------------------------
// Fused forward FFTs: blocks [0,256) -> inputs->Xhat, [256,512) -> kernel->What.
// Per block: one row (b or f) and a 16-wide channel slice. smem = 512*16*8 = 64KB.
// ---------------------------------------------------------------------------
__global__ void __launch_bounds__(256)
fft3d_fwd2_kernel(const float* __restrict__ inA, const float* __restrict__ inB,
                  float2* __restrict__ outA, float2* __restrict__ outB) {
    extern __shared__ float2 V[];
    int blk = blockIdx.x;
    const float* in;
    float2* out;
    long rowStride, sStride;
    if (blk < 256) { in = inA; out = outA; rowStride = 32768; sStride = 64; }
    else           { blk -= 256; in = inB; out = outB; rowStride = 64; sStride = 4096; }
    const int row = blk >> 2, c0 = (blk & 3) * 16;
    const int tid = threadIdx.x;

    // Load: float4 (4 channels) per thread per iter. 8192 floats / 4 / 256 = 8 iters.
    const float* base = in + (long)row * rowStride + c0;
    for (int i4 = tid; i4 < 2048; i4 += 256) {
        const int s = i4 >> 2, cc = (i4 & 3) * 4;
        const float4 v = *(const float4*)(base + (long)s * sStride + cc);
        V[s * 16 + cc + 0] = make_float2(v.x, 0.f);
        V[s * 16 + cc + 1] = make_float2(v.y, 0.f);
        V[s * 16 + cc + 2] = make_float2(v.z, 0.f);
        V[s * 16 + cc + 3] = make_float2(v.w, 0.f);
    }
    __syncthreads();

    fft3d_passes16<0>(V);

    // Store: float4 = 2 complex per thread per iter. 8192 complex / 2 / 256 = 16 iters.
    float4* o4 = (float4*)(out + row * 64 + c0);
    const float4* V4 = (const float4*)V;
    for (int i2 = tid; i2 < 4096; i2 += 256) {
        const int s = i2 >> 3, c2 = i2 & 7;
        o4[s * 2048 + c2] = V4[s * 8 + c2];
    }
}

// ---------------------------------------------------------------------------
// Hermitian pointwise batched complex GEMM: canonical k only (k <= neg(k)),
// write Y(k) and conj into Y(neg(k)).
// ---------------------------------------------------------------------------
__global__ void __launch_bounds__(256)
pointwise_kernel(const float2* __restrict__ Xh, const float2* __restrict__ Wh,
                 float2* __restrict__ Yh) {
    const int k = blockIdx.x;
    const int kx = k >> 6, ky = (k >> 3) & 7, kz = k & 7;
    const int neg = (((8 - kx) & 7) << 6) | (((8 - ky) & 7) << 3) | ((8 - kz) & 7);
    if (k > neg) return;

    extern __shared__ float2 sm[];
    float2* As = sm;            // [c][b], stride 65
    float2* Bs = sm + 64 * 65;  // [c][f], stride 65
    const int tid = threadIdx.x;

    const float4* xk4 = (const float4*)(Xh + (long)k * 4096);
    const float4* wk4 = (const float4*)(Wh + (long)k * 4096);
    for (int i = tid; i < 2048; i += 256) {  // i = complex pair index
        const int rowi = i >> 5, c = (i & 31) * 2;
        const float4 xa = xk4[i], wb = wk4[i];
        As[c * 65 + rowi] = make_float2(xa.x, xa.y);
        As[(c + 1) * 65 + rowi] = make_float2(xa.z, xa.w);
        Bs[c * 65 + rowi] = make_float2(wb.x, wb.y);
        Bs[(c + 1) * 65 + rowi] = make_float2(wb.z, wb.w);
    }
    __syncthreads();

    const int ft = tid & 15;
    const int bt = tid >> 4;
    float accx[4][4] = {}, accy[4][4] = {};
    float ax[4], ay[4], bx[4], by[4];

#pragma unroll 2
    for (int c = 0; c < 64; ++c) {
#pragma unroll
        for (int i = 0; i < 4; ++i) {
            const float2 t = As[c * 65 + bt + 16 * i];
            ax[i] = t.x; ay[i] = t.y;
        }
#pragma unroll
        for (int j = 0; j < 4; ++j) {
            const float2 t = Bs[c * 65 + ft + 16 * j];
            bx[j] = t.x; by[j] = t.y;
        }
#pragma unroll
        for (int i = 0; i < 4; ++i)
#pragma unroll
            for (int j = 0; j < 4; ++j) {
                accx[i][j] += ax[i] * bx[j] - ay[i] * by[j];
                accy[i][j] += ax[i] * by[j] + ay[i] * bx[j];
            }
    }

    float2* yk = Yh + (long)k * 4096;
    if (k == neg) {
#pragma unroll
        for (int i = 0; i < 4; ++i)
#pragma unroll
            for (int j = 0; j < 4; ++j)
                yk[(bt + 16 * i) * 64 + ft + 16 * j] = make_float2(accx[i][j], accy[i][j]);
    } else {
        float2* yn = Yh + (long)neg * 4096;
#pragma unroll
        for (int i = 0; i < 4; ++i)
#pragma unroll
            for (int j = 0; j < 4; ++j) {
                const int idx = (bt + 16 * i) * 64 + ft + 16 * j;
                yk[idx] = make_float2(accx[i][j], accy[i][j]);
                yn[idx] = make_float2(accx[i][j], -accy[i][j]);
            }
    }
}

// ---------------------------------------------------------------------------
// Inverse FFT + real part + 1/512 + bias. One block per (b, 16-wide f slice).
// ---------------------------------------------------------------------------
__global__ void __launch_bounds__(256)
ifft3d_kernel(const float2* __restrict__ Yh, const float* __restrict__ bias,
              float* __restrict__ out) {
    extern __shared__ float2 V[];
    const int b = blockIdx.x >> 2, f0 = (blockIdx.x & 3) * 16;
    const int tid = threadIdx.x;

    const float4* y4 = (const float4*)(Yh + b * 64 + f0);
    float4* V4 = (float4*)V;
    for (int i2 = tid; i2 < 4096; i2 += 256) {
        const int s = i2 >> 3, c2 = i2 & 7;
        V4[s * 8 + c2] = y4[s * 2048 + c2];
    }
    __syncthreads();

    fft3d_passes16<1>(V);

    // out[b,s,f0+f]: 16 floats per s = 4 float4 per s.
    float4* o4 = (float4*)(out + ((long)b * 512) * 64 + f0);
    for (int i4 = tid; i4 < 2048; i4 += 256) {
        const int s = i4 >> 2, cc = (i4 & 3) * 4;
        float4 r;
        r.x = V[s * 16 + cc + 0].x * (1.f / 512.f) + bias[f0 + cc + 0];
        r.y = V[s * 16 + cc + 1].x * (1.f / 512.f) + bias[f0 + cc + 1];
        r.z = V[s * 16 + cc + 2].x * (1.f / 512.f) + bias[f0 + cc + 2];
        r.w = V[s * 16 + cc + 3].x * (1.f / 512.f) + bias[f0 + cc + 3];
        o4[s * 16 + (cc >> 2)] = r;
    }
}

// ---------------------------------------------------------------------------
extern "C" void kernel_launch(void* const* d_in, const int* in_sizes, int n_in,
                              void* d_out, int out_size) {
    const float* inputs = (const float*)d_in[0];
    const float* kern   = (const float*)d_in[1];
    const float* bias   = (const float*)d_in[2];
    float* out = (float*)d_out;

    float2 *Xh, *Wh, *Yh;
    cudaGetSymbolAddress((void**)&Xh, g_Xhat);
    cudaGetSymbolAddress((void**)&Wh, g_What);
    cudaGetSymbolAddress((void**)&Yh, g_Yhat);

    const int smemFFT = 512 * 16 * (int)sizeof(float2);    // 65536 B
    const int smemPW  = 2 * 64 * 65 * (int)sizeof(float2); // 66560 B
    cudaFuncSetAttribute(fft3d_fwd2_kernel, cudaFuncAttributeMaxDynamicSharedMemorySize, smemFFT);
    cudaFuncSetAttribute(ifft3d_kernel,     cudaFuncAttributeMaxDynamicSharedMemorySize, smemFFT);
    cudaFuncSetAttribute(pointwise_kernel,  cudaFuncAttributeMaxDynamicSharedMemorySize, smemPW);

    fft3d_fwd2_kernel<<<512, 256, smemFFT>>>(inputs, kern, Xh, Wh);
    pointwise_kernel<<<512, 256, smemPW>>>(Xh, Wh, Yh);
    ifft3d_kernel<<<256, 256, smemFFT>>>(Yh, bias, out);
}

// round 3
// speedup vs baseline: 1.8798x; 1.4421x over previous
#include <cuda_runtime.h>

// ============================================================================
// TorusConv3D via FFT diagonalization (round 3).
// Round-3 changes:
//  - FFT kernels fuse the z-axis pass with the global load and the x-axis pass
//    with the global store (2 STS + 2 LDS per point instead of 4+4).
//  - Pointwise GEMM uses packed fma.rn.f32x2 (2 packed FMA per complex MAC).
//  - Pointwise launches exactly the 260 canonical Hermitian frequencies
//    (single wave at 2 CTAs/SM), writing the conjugate partner directly.
// ============================================================================

#define R2 0.70710678118654752440f

// g_Xhat[k*4096 + b*64 + c], g_What[k*4096 + f*64 + c], g_Yhat[k*4096 + b*64 + f]
__device__ float2 g_Xhat[512 * 64 * 64];
__device__ float2 g_What[512 * 64 * 64];
__device__ float2 g_Yhat[512 * 64 * 64];

// ---------------------------------------------------------------------------
// Radix-2 DIT 8-point FFT, in place. Forward = e^{-2pi i nk/8}; INV conjugates.
// ---------------------------------------------------------------------------
__device__ __forceinline__ float2 cadd(float2 a, float2 b) { return make_float2(a.x + b.x, a.y + b.y); }
__device__ __forceinline__ float2 csub(float2 a, float2 b) { return make_float2(a.x - b.x, a.y - b.y); }
template <int INV>
__device__ __forceinline__ float2 mulmi(float2 a) {
    return INV ? make_float2(-a.y, a.x) : make_float2(a.y, -a.x);
}
template <int INV>
__device__ __forceinline__ float2 mulw1(float2 a) {
    return INV ? make_float2(R2 * (a.x - a.y), R2 * (a.y + a.x))
               : make_float2(R2 * (a.x + a.y), R2 * (a.y - a.x));
}
template <int INV>
__device__ __forceinline__ float2 mulw3(float2 a) {
    return INV ? make_float2(R2 * (-a.x - a.y), R2 * (a.x - a.y))
               : make_float2(R2 * (a.y - a.x), R2 * (-a.x - a.y));
}

template <int INV>
__device__ __forceinline__ void fft8(float2* v) {
    float2 t0 = cadd(v[0], v[4]), t1 = csub(v[0], v[4]);
    float2 t2 = cadd(v[2], v[6]), t3 = csub(v[2], v[6]);
    float2 t4 = cadd(v[1], v[5]), t5 = csub(v[1], v[5]);
    float2 t6 = cadd(v[3], v[7]), t7 = csub(v[3], v[7]);
    float2 a0 = cadd(t0, t2), a1 = csub(t0, t2);
    float2 m3 = mulmi<INV>(t3);
    float2 a2 = cadd(t1, m3), a3 = csub(t1, m3);
    float2 b0 = cadd(t4, t6), b1 = csub(t4, t6);
    float2 m7 = mulmi<INV>(t7);
    float2 b2 = cadd(t5, m7), b3 = csub(t5, m7);
    float2 mb1 = mulmi<INV>(b1);
    float2 w1 = mulw1<INV>(b2);
    float2 w3 = mulw3<INV>(b3);
    v[0] = cadd(a0, b0); v[4] = csub(a0, b0);
    v[2] = cadd(a1, mb1); v[6] = csub(a1, mb1);
    v[1] = cadd(a2, w1); v[5] = csub(a2, w1);
    v[3] = cadd(a3, w3); v[7] = csub(a3, w3);
}

// ---------------------------------------------------------------------------
// Packed f32x2 helpers (Blackwell).
// ---------------------------------------------------------------------------
__device__ __forceinline__ unsigned long long pack2(float lo, float hi) {
    unsigned long long r;
    asm("mov.b64 %0, {%1, %2};" : "=l"(r) : "f"(lo), "f"(hi));
    return r;
}
__device__ __forceinline__ unsigned long long fma2(unsigned long long a, unsigned long long b,
                                                   unsigned long long c) {
    unsigned long long d;
    asm("fma.rn.f32x2 %0, %1, %2, %3;" : "=l"(d) : "l"(a), "l"(b), "l"(c));
    return d;
}
__device__ __forceinline__ float2 unpack2(unsigned long long v) {
    float lo, hi;
    asm("mov.b64 {%0, %1}, %2;" : "=f"(lo), "=f"(hi) : "l"(v));
    return make_float2(lo, hi);
}

// ---------------------------------------------------------------------------
// Forward FFT, fused ends. One block: one row (b or f) + 16-channel slice.
// smem V[s*16 + c], s = x*64+y*8+z. 256 threads: c = tid&15, pp = tid>>4.
// Phase1: global load z-line -> fft8 -> STS. Phase2: smem y-pass.
// Phase3: LDS x-line -> fft8 -> STG to out[k*4096 + row*64 + c0+c].
// Blocks [0,256) -> inputs->Xhat, [256,512) -> kernel->What.
// ---------------------------------------------------------------------------
__global__ void __launch_bounds__(256, 3)
fft3d_fwd2_kernel(const float* __restrict__ inA, const float* __restrict__ inB,
                  float2* __restrict__ outA, float2* __restrict__ outB) {
    extern __shared__ float2 V[];
    int blk = blockIdx.x;
    const float* in;
    float2* out;
    long rowStride, sStride;
    if (blk < 256) { in = inA; out = outA; rowStride = 32768; sStride = 64; }
    else           { blk -= 256; in = inB; out = outB; rowStride = 64; sStride = 4096; }
    const int row = blk >> 2, c0 = (blk & 3) * 16;
    const int tid = threadIdx.x;
    const int c = tid & 15, pp = tid >> 4;

    const float* base = in + (long)row * rowStride + c0 + c;
    float2 buf[8];

    // Phase 1: z-axis in registers, fused with global load. t = (x,y) line id.
    for (int m = 0; m < 4; ++m) {
        const int t = pp + 16 * m;          // 0..63, s = 8t + z
#pragma unroll
        for (int z = 0; z < 8; ++z)
            buf[z] = make_float2(base[(long)(8 * t + z) * sStride], 0.f);
        fft8<0>(buf);
#pragma unroll
        for (int z = 0; z < 8; ++z) V[(8 * t + z) * 16 + c] = buf[z];
    }
    __syncthreads();

    // Phase 2: y-axis through smem. t = (x,z): x=t>>3, z=t&7. stride 8*16=128.
    for (int m = 0; m < 4; ++m) {
        const int t = pp + 16 * m;
        const int b0 = ((t >> 3) * 64 + (t & 7)) * 16 + c;
#pragma unroll
        for (int y = 0; y < 8; ++y) buf[y] = V[b0 + y * 128];
        fft8<0>(buf);
#pragma unroll
        for (int y = 0; y < 8; ++y) V[b0 + y * 128] = buf[y];
    }
    __syncthreads();

    // Phase 3: x-axis fused with global store. t = (y,z): base = t*16+c, stride 1024.
    float2* og = out + row * 64 + c0 + c;
    for (int m = 0; m < 4; ++m) {
        const int t = pp + 16 * m;
#pragma unroll
        for (int x = 0; x < 8; ++x) buf[x] = V[t * 16 + c + x * 1024];
        fft8<0>(buf);
#pragma unroll
        for (int x = 0; x < 8; ++x) og[(long)(x * 64 + t) * 4096] = buf[x];
    }
}

// ---------------------------------------------------------------------------
// Hermitian pointwise complex GEMM, canonical frequencies only (260 blocks).
// Y[b,f] = sum_c A[b,c]*B[f,c]; conj written to the negated frequency.
// ---------------------------------------------------------------------------
__global__ void __launch_bounds__(256)
pointwise_kernel(const float2* __restrict__ Xh, const float2* __restrict__ Wh,
                 float2* __restrict__ Yh) {
    // rank -> canonical (kx,ky,kz): per-axis negation d -> (8-d)&7.
    const int rank = blockIdx.x;
    int kx, ky, kz;
    if (rank < 192) {
        kx = 1 + rank / 64; const int r = rank & 63; ky = r >> 3; kz = r & 7;
    } else if (rank < 240) {
        const int r = rank - 192; kx = (r / 24) * 4;
        const int r2 = r % 24; ky = 1 + r2 / 8; kz = r2 & 7;
    } else {
        const int r = rank - 240; kx = (r / 10) * 4;
        const int r2 = r % 10; ky = (r2 / 5) * 4; kz = r2 % 5;
    }
    const int k = (kx << 6) | (ky << 3) | kz;
    const int neg = (((8 - kx) & 7) << 6) | (((8 - ky) & 7) << 3) | ((8 - kz) & 7);

    extern __shared__ float2 sm[];
    float2* As = sm;            // [c][b], stride 65
    float2* Bs = sm + 64 * 65;  // [c][f], stride 65
    const int tid = threadIdx.x;

    const float4* xk4 = (const float4*)(Xh + (long)k * 4096);
    const float4* wk4 = (const float4*)(Wh + (long)k * 4096);
    for (int i = tid; i < 2048; i += 256) {
        const int rowi = i >> 5, cc = (i & 31) * 2;
        const float4 xa = xk4[i], wb = wk4[i];
        As[cc * 65 + rowi] = make_float2(xa.x, xa.y);
        As[(cc + 1) * 65 + rowi] = make_float2(xa.z, xa.w);
        Bs[cc * 65 + rowi] = make_float2(wb.x, wb.y);
        Bs[(cc + 1) * 65 + rowi] = make_float2(wb.z, wb.w);
    }
    __syncthreads();

    const int ft = tid & 15;
    const int bt = tid >> 4;
    unsigned long long acc[4][4];
#pragma unroll
    for (int i = 0; i < 4; ++i)
#pragma unroll
        for (int j = 0; j < 4; ++j) acc[i][j] = 0ULL;

    unsigned long long axax[4], nay[4], bxy[4], byx[4];
#pragma unroll 2
    for (int cc = 0; cc < 64; ++cc) {
#pragma unroll
        for (int i = 0; i < 4; ++i) {
            const float2 t = As[cc * 65 + bt + 16 * i];
            axax[i] = pack2(t.x, t.x);
            nay[i] = pack2(-t.y, t.y);
        }
#pragma unroll
        for (int j = 0; j < 4; ++j) {
            const float2 t = Bs[cc * 65 + ft + 16 * j];
            bxy[j] = pack2(t.x, t.y);
            byx[j] = pack2(t.y, t.x);
        }
#pragma unroll
        for (int i = 0; i < 4; ++i)
#pragma unroll
            for (int j = 0; j < 4; ++j) {
                acc[i][j] = fma2(axax[i], bxy[j], acc[i][j]);  // (+ax*bx, +ax*by)
                acc[i][j] = fma2(nay[i], byx[j], acc[i][j]);   // (-ay*by, +ay*bx)
            }
    }

    float2* yk = Yh + (long)k * 4096;
    if (k == neg) {
#pragma unroll
        for (int i = 0; i < 4; ++i)
#pragma unroll
            for (int j = 0; j < 4; ++j)
                yk[(bt + 16 * i) * 64 + ft + 16 * j] = unpack2(acc[i][j]);
    } else {
        float2* yn = Yh + (long)neg * 4096;
#pragma unroll
        for (int i = 0; i < 4; ++i)
#pragma unroll
            for (int j = 0; j < 4; ++j) {
                const float2 r = unpack2(acc[i][j]);
                const int idx = (bt + 16 * i) * 64 + ft + 16 * j;
                yk[idx] = r;
                yn[idx] = make_float2(r.x, -r.y);
            }
    }
}

// ---------------------------------------------------------------------------
// Inverse FFT, fused ends. One block per (b, 16-wide f slice).
// Phase1: global load z-line from Yhat -> fft8 -> STS.
// Phase3: LDS x-line -> fft8 -> real part * 1/512 + bias -> STG.
// ---------------------------------------------------------------------------
__global__ void __launch_bounds__(256, 3)
ifft3d_kernel(const float2* __restrict__ Yh, const float* __restrict__ bias,
              float* __restrict__ out) {
    extern __shared__ float2 V[];
    const int b = blockIdx.x >> 2, f0 = (blockIdx.x & 3) * 16;
    const int tid = threadIdx.x;
    const int c = tid & 15, pp = tid >> 4;
    const float bv = __ldg(bias + f0 + c);

    const float2* yg = Yh + b * 64 + f0 + c;
    float2 buf[8];

    // Phase 1: z-axis fused with load. s = 8t + z.
    for (int m = 0; m < 4; ++m) {
        const int t = pp + 16 * m;
#pragma unroll
        for (int z = 0; z < 8; ++z) buf[z] = yg[(long)(8 * t + z) * 4096];
        fft8<1>(buf);
#pragma unroll
        for (int z = 0; z < 8; ++z) V[(8 * t + z) * 16 + c] = buf[z];
    }
    __syncthreads();

    // Phase 2: y-axis.
    for (int m = 0; m < 4; ++m) {
        const int t = pp + 16 * m;
        const int b0 = ((t >> 3) * 64 + (t & 7)) * 16 + c;
#pragma unroll
        for (int y = 0; y < 8; ++y) buf[y] = V[b0 + y * 128];
        fft8<1>(buf);
#pragma unroll
        for (int y = 0; y < 8; ++y) V[b0 + y * 128] = buf[y];
    }
    __syncthreads();

    // Phase 3: x-axis fused with output store (real part + scale + bias).
    float* og = out + ((long)b * 512) * 64 + f0 + c;
    for (int m = 0; m < 4; ++m) {
        const int t = pp + 16 * m;
#pragma unroll
        for (int x = 0; x < 8; ++x) buf[x] = V[t * 16 + c + x * 1024];
        fft8<1>(buf);
#pragma unroll
        for (int x = 0; x < 8; ++x)
            og[(long)(x * 64 + t) * 64] = buf[x].x * (1.f / 512.f) + bv;
    }
}

// ---------------------------------------------------------------------------
extern "C" void kernel_launch(void* const* d_in, const int* in_sizes, int n_in,
                              void* d_out, int out_size) {
    const float* inputs = (const float*)d_in[0];
    const float* kern   = (const float*)d_in[1];
    const float* bias   = (const float*)d_in[2];
    float* out = (float*)d_out;

    float2 *Xh, *Wh, *Yh;
    cudaGetSymbolAddress((void**)&Xh, g_Xhat);
    cudaGetSymbolAddress((void**)&Wh, g_What);
    cudaGetSymbolAddress((void**)&Yh, g_Yhat);

    const int smemFFT = 512 * 16 * (int)sizeof(float2);    // 65536 B
    const int smemPW  = 2 * 64 * 65 * (int)sizeof(float2); // 66560 B
    cudaFuncSetAttribute(fft3d_fwd2_kernel, cudaFuncAttributeMaxDynamicSharedMemorySize, smemFFT);
    cudaFuncSetAttribute(ifft3d_kernel,     cudaFuncAttributeMaxDynamicSharedMemorySize, smemFFT);
    cudaFuncSetAttribute(pointwise_kernel,  cudaFuncAttributeMaxDynamicSharedMemorySize, smemPW);

    fft3d_fwd2_kernel<<<512, 256, smemFFT>>>(inputs, kern, Xh, Wh);
    pointwise_kernel<<<260, 256, smemPW>>>(Xh, Wh, Yh);
    ifft3d_kernel<<<256, 256, smemFFT>>>(Yh, bias, out);
}

// round 4
// speedup vs baseline: 2.2893x; 1.2179x over previous
#include <cuda_runtime.h>

// ============================================================================
// TorusConv3D via FFT diagonalization (round 4).
// Round-4: real-pair packing everywhere.
//  - Forward FFT transforms P_j = X_{2j} + i*X_{2j+1} (32 packed columns), so
//    forward flops and spectrum storage are halved (Xp/Wp: 8.4 MB each).
//  - Pointwise unpacks (k, -k) pairs on the fly, runs the same 64-channel
//    complex GEMM, then packs output f-pairs Z = Y_{2f} + i*Y_{2f+1} via
//    shfl, halving Yhat storage (8.4 MB) and inverse-FFT work.
//  - Inverse FFT output: real part -> channel 2f, imag part -> channel 2f+1.
// ============================================================================

#define R2 0.70710678118654752440f

// Packed spectra: g_Xp[k*2048 + b*32 + j], g_Wp[k*2048 + f*32 + j],
//                 g_Z [k*2048 + b*32 + fp]
__device__ float2 g_Xp[512 * 2048];
__device__ float2 g_Wp[512 * 2048];
__device__ float2 g_Z[512 * 2048];

// ---------------------------------------------------------------------------
// Radix-2 DIT 8-point FFT, in place. Forward = e^{-2pi i nk/8}; INV conjugates.
// ---------------------------------------------------------------------------
__device__ __forceinline__ float2 cadd(float2 a, float2 b) { return make_float2(a.x + b.x, a.y + b.y); }
__device__ __forceinline__ float2 csub(float2 a, float2 b) { return make_float2(a.x - b.x, a.y - b.y); }
template <int INV>
__device__ __forceinline__ float2 mulmi(float2 a) {
    return INV ? make_float2(-a.y, a.x) : make_float2(a.y, -a.x);
}
template <int INV>
__device__ __forceinline__ float2 mulw1(float2 a) {
    return INV ? make_float2(R2 * (a.x - a.y), R2 * (a.y + a.x))
               : make_float2(R2 * (a.x + a.y), R2 * (a.y - a.x));
}
template <int INV>
__device__ __forceinline__ float2 mulw3(float2 a) {
    return INV ? make_float2(R2 * (-a.x - a.y), R2 * (a.x - a.y))
               : make_float2(R2 * (a.y - a.x), R2 * (-a.x - a.y));
}

template <int INV>
__device__ __forceinline__ void fft8(float2* v) {
    float2 t0 = cadd(v[0], v[4]), t1 = csub(v[0], v[4]);
    float2 t2 = cadd(v[2], v[6]), t3 = csub(v[2], v[6]);
    float2 t4 = cadd(v[1], v[5]), t5 = csub(v[1], v[5]);
    float2 t6 = cadd(v[3], v[7]), t7 = csub(v[3], v[7]);
    float2 a0 = cadd(t0, t2), a1 = csub(t0, t2);
    float2 m3 = mulmi<INV>(t3);
    float2 a2 = cadd(t1, m3), a3 = csub(t1, m3);
    float2 b0 = cadd(t4, t6), b1 = csub(t4, t6);
    float2 m7 = mulmi<INV>(t7);
    float2 b2 = cadd(t5, m7), b3 = csub(t5, m7);
    float2 mb1 = mulmi<INV>(b1);
    float2 w1 = mulw1<INV>(b2);
    float2 w3 = mulw3<INV>(b3);
    v[0] = cadd(a0, b0); v[4] = csub(a0, b0);
    v[2] = cadd(a1, mb1); v[6] = csub(a1, mb1);
    v[1] = cadd(a2, w1); v[5] = csub(a2, w1);
    v[3] = cadd(a3, w3); v[7] = csub(a3, w3);
}

// ---------------------------------------------------------------------------
// Packed f32x2 helpers.
// ---------------------------------------------------------------------------
__device__ __forceinline__ unsigned long long pack2(float lo, float hi) {
    unsigned long long r;
    asm("mov.b64 %0, {%1, %2};" : "=l"(r) : "f"(lo), "f"(hi));
    return r;
}
__device__ __forceinline__ unsigned long long fma2(unsigned long long a, unsigned long long b,
                                                   unsigned long long c) {
    unsigned long long d;
    asm("fma.rn.f32x2 %0, %1, %2, %3;" : "=l"(d) : "l"(a), "l"(b), "l"(c));
    return d;
}
__device__ __forceinline__ float2 unpack2(unsigned long long v) {
    float lo, hi;
    asm("mov.b64 {%0, %1}, %2;" : "=f"(lo), "=f"(hi) : "l"(v));
    return make_float2(lo, hi);
}

// ---------------------------------------------------------------------------
// Forward packed FFT. One block: one row (b or f) + 16 packed-pair columns.
// smem V[s*16 + c], s = x*64+y*8+z. 256 threads: c = tid&15, pp = tid>>4.
// Blocks [0,128) -> inputs->Xp, [128,256) -> kernel->Wp.
// Output: out[k*2048 + row*32 + j0 + c].
// ---------------------------------------------------------------------------
__global__ void __launch_bounds__(256, 3)
fft3d_fwd_packed(const float* __restrict__ inA, const float* __restrict__ inB,
                 float2* __restrict__ outA, float2* __restrict__ outB) {
    extern __shared__ float2 V[];
    int blk = blockIdx.x;
    const float* in;
    float2* out;
    long rowStride, sStride;
    if (blk < 128) { in = inA; out = outA; rowStride = 32768; sStride = 64; }
    else           { blk -= 128; in = inB; out = outB; rowStride = 64; sStride = 4096; }
    const int row = blk >> 1, j0 = (blk & 1) * 16;
    const int tid = threadIdx.x;
    const int c = tid & 15, pp = tid >> 4;

    // Pair column j0+c occupies input floats 2*(j0+c), 2*(j0+c)+1.
    const float* base = in + (long)row * rowStride + 2 * (j0 + c);
    float2 buf[8];

    // Phase 1: z-axis fused with packed load (float2 = one complex point).
    for (int m = 0; m < 4; ++m) {
        const int t = pp + 16 * m;  // (x,y) line id, s = 8t + z
#pragma unroll
        for (int z = 0; z < 8; ++z)
            buf[z] = *(const float2*)(base + (long)(8 * t + z) * sStride);
        fft8<0>(buf);
#pragma unroll
        for (int z = 0; z < 8; ++z) V[(8 * t + z) * 16 + c] = buf[z];
    }
    __syncthreads();

    // Phase 2: y-axis through smem. t = (x,z).
    for (int m = 0; m < 4; ++m) {
        const int t = pp + 16 * m;
        const int b0 = ((t >> 3) * 64 + (t & 7)) * 16 + c;
#pragma unroll
        for (int y = 0; y < 8; ++y) buf[y] = V[b0 + y * 128];
        fft8<0>(buf);
#pragma unroll
        for (int y = 0; y < 8; ++y) V[b0 + y * 128] = buf[y];
    }
    __syncthreads();

    // Phase 3: x-axis fused with global store. t = (ky,kz).
    float2* og = out + row * 32 + j0 + c;
    for (int m = 0; m < 4; ++m) {
        const int t = pp + 16 * m;
#pragma unroll
        for (int x = 0; x < 8; ++x) buf[x] = V[t * 16 + c + x * 1024];
        fft8<0>(buf);
#pragma unroll
        for (int x = 0; x < 8; ++x) og[(long)(x * 64 + t) * 2048] = buf[x];
    }
}

// ---------------------------------------------------------------------------
// Hermitian pointwise complex GEMM over canonical frequencies (260 blocks).
// Fill: unpack packed spectra using (k, -k): X_{2j} = (P(k)+conj(P(-k)))/2,
//       X_{2j+1} = -i*(P(k)-conj(P(-k)))/2.
// Drain: pack f-pairs Z(k) = Y_{2f}+iY_{2f+1}, Z(-k) from conjugates, via shfl.
// ---------------------------------------------------------------------------
__global__ void __launch_bounds__(256)
pointwise_kernel(const float2* __restrict__ Xp, const float2* __restrict__ Wp,
                 float2* __restrict__ Zh) {
    const int rank = blockIdx.x;
    int kx, ky, kz;
    if (rank < 192) {
        kx = 1 + rank / 64; const int r = rank & 63; ky = r >> 3; kz = r & 7;
    } else if (rank < 240) {
        const int r = rank - 192; kx = (r / 24) * 4;
        const int r2 = r % 24; ky = 1 + r2 / 8; kz = r2 & 7;
    } else {
        const int r = rank - 240; kx = (r / 10) * 4;
        const int r2 = r % 10; ky = (r2 / 5) * 4; kz = r2 % 5;
    }
    const int k = (kx << 6) | (ky << 3) | kz;
    const int neg = (((8 - kx) & 7) << 6) | (((8 - ky) & 7) << 3) | ((8 - kz) & 7);

    extern __shared__ float2 sm[];
    float2* As = sm;            // [c][b], stride 65
    float2* Bs = sm + 64 * 65;  // [c][f], stride 65
    const int tid = threadIdx.x;

    const float2* xk = Xp + (long)k * 2048;
    const float2* xn = Xp + (long)neg * 2048;
    const float2* wk = Wp + (long)k * 2048;
    const float2* wn = Wp + (long)neg * 2048;
    for (int i = tid; i < 2048; i += 256) {
        const int j = i & 31, rowi = i >> 5;
        const int c0 = 2 * j, c1 = 2 * j + 1;
        {
            const float2 Pk = xk[i], Pn = xn[i];
            As[c0 * 65 + rowi] = make_float2(0.5f * (Pk.x + Pn.x), 0.5f * (Pk.y - Pn.y));
            As[c1 * 65 + rowi] = make_float2(0.5f * (Pk.y + Pn.y), 0.5f * (Pn.x - Pk.x));
        }
        {
            const float2 Pk = wk[i], Pn = wn[i];
            Bs[c0 * 65 + rowi] = make_float2(0.5f * (Pk.x + Pn.x), 0.5f * (Pk.y - Pn.y));
            Bs[c1 * 65 + rowi] = make_float2(0.5f * (Pk.y + Pn.y), 0.5f * (Pn.x - Pk.x));
        }
    }
    __syncthreads();

    const int ft = tid & 15;
    const int bt = tid >> 4;
    unsigned long long acc[4][4];
#pragma unroll
    for (int i = 0; i < 4; ++i)
#pragma unroll
        for (int j = 0; j < 4; ++j) acc[i][j] = 0ULL;

    unsigned long long axax[4], nay[4], bxy[4], byx[4];
#pragma unroll 2
    for (int cc = 0; cc < 64; ++cc) {
#pragma unroll
        for (int i = 0; i < 4; ++i) {
            const float2 t = As[cc * 65 + bt + 16 * i];
            axax[i] = pack2(t.x, t.x);
            nay[i] = pack2(-t.y, t.y);
        }
#pragma unroll
        for (int j = 0; j < 4; ++j) {
            const float2 t = Bs[cc * 65 + ft + 16 * j];
            bxy[j] = pack2(t.x, t.y);
            byx[j] = pack2(t.y, t.x);
        }
#pragma unroll
        for (int i = 0; i < 4; ++i)
#pragma unroll
            for (int j = 0; j < 4; ++j) {
                acc[i][j] = fma2(axax[i], bxy[j], acc[i][j]);  // (+ax*bx, +ax*by)
                acc[i][j] = fma2(nay[i], byx[j], acc[i][j]);   // (-ay*by, +ay*bx)
            }
    }

    // Drain: pack f-pairs. Even-ft lanes own fp = ft/2 + 8j.
    float2* zk = Zh + (long)k * 2048;
    float2* zn = Zh + (long)neg * 2048;
    const bool self = (k == neg);
    const bool even = (ft & 1) == 0;
    const int fp0 = ft >> 1;
#pragma unroll
    for (int i = 0; i < 4; ++i)
#pragma unroll
        for (int j = 0; j < 4; ++j) {
            const unsigned long long part = __shfl_xor_sync(0xffffffffu, acc[i][j], 1);
            if (even) {
                const float2 Y0 = unpack2(acc[i][j]);  // f = 2fp
                const float2 Y1 = unpack2(part);       // f = 2fp+1
                const int idx = (bt + 16 * i) * 32 + fp0 + 8 * j;
                zk[idx] = make_float2(Y0.x - Y1.y, Y0.y + Y1.x);
                if (!self) zn[idx] = make_float2(Y0.x + Y1.y, Y1.x - Y0.y);
            }
        }
}

// ---------------------------------------------------------------------------
// Inverse packed FFT + bias. One block per (b, 16 fp columns).
// IFFT(Y_{2f} + i Y_{2f+1}) = out_{2f} + i out_{2f+1} (both real).
// ---------------------------------------------------------------------------
__global__ void __launch_bounds__(256, 3)
ifft3d_packed(const float2* __restrict__ Zh, const float* __restrict__ bias,
              float* __restrict__ out) {
    extern __shared__ float2 V[];
    const int b = blockIdx.x >> 1, fp0 = (blockIdx.x & 1) * 16;
    const int tid = threadIdx.x;
    const int c = tid & 15, pp = tid >> 4;
    const float2 bv = ((const float2*)bias)[fp0 + c];  // bias[2fp], bias[2fp+1]

    const float2* yg = Zh + b * 32 + fp0 + c;
    float2 buf[8];

    // Phase 1: z-axis fused with load.
    for (int m = 0; m < 4; ++m) {
        const int t = pp + 16 * m;
#pragma unroll
        for (int z = 0; z < 8; ++z) buf[z] = yg[(long)(8 * t + z) * 2048];
        fft8<1>(buf);
#pragma unroll
        for (int z = 0; z < 8; ++z) V[(8 * t + z) * 16 + c] = buf[z];
    }
    __syncthreads();

    // Phase 2: y-axis.
    for (int m = 0; m < 4; ++m) {
        const int t = pp + 16 * m;
        const int b0 = ((t >> 3) * 64 + (t & 7)) * 16 + c;
#pragma unroll
        for (int y = 0; y < 8; ++y) buf[y] = V[b0 + y * 128];
        fft8<1>(buf);
#pragma unroll
        for (int y = 0; y < 8; ++y) V[b0 + y * 128] = buf[y];
    }
    __syncthreads();

    // Phase 3: x-axis fused with store: re -> f=2fp, im -> f=2fp+1.
    float2* og = (float2*)out + (long)b * 512 * 32 + fp0 + c;
    for (int m = 0; m < 4; ++m) {
        const int t = pp + 16 * m;
#pragma unroll
        for (int x = 0; x < 8; ++x) buf[x] = V[t * 16 + c + x * 1024];
        fft8<1>(buf);
#pragma unroll
        for (int x = 0; x < 8; ++x)
            og[(long)(x * 64 + t) * 32] =
                make_float2(buf[x].x * (1.f / 512.f) + bv.x,
                            buf[x].y * (1.f / 512.f) + bv.y);
    }
}

// ---------------------------------------------------------------------------
extern "C" void kernel_launch(void* const* d_in, const int* in_sizes, int n_in,
                              void* d_out, int out_size) {
    const float* inputs = (const float*)d_in[0];
    const float* kern   = (const float*)d_in[1];
    const float* bias   = (const float*)d_in[2];
    float* out = (float*)d_out;

    float2 *Xp, *Wp, *Zh;
    cudaGetSymbolAddress((void**)&Xp, g_Xp);
    cudaGetSymbolAddress((void**)&Wp, g_Wp);
    cudaGetSymbolAddress((void**)&Zh, g_Z);

    const int smemFFT = 512 * 16 * (int)sizeof(float2);    // 65536 B
    const int smemPW  = 2 * 64 * 65 * (int)sizeof(float2); // 66560 B
    cudaFuncSetAttribute(fft3d_fwd_packed, cudaFuncAttributeMaxDynamicSharedMemorySize, smemFFT);
    cudaFuncSetAttribute(ifft3d_packed,    cudaFuncAttributeMaxDynamicSharedMemorySize, smemFFT);
    cudaFuncSetAttribute(pointwise_kernel, cudaFuncAttributeMaxDynamicSharedMemorySize, smemPW);

    fft3d_fwd_packed<<<256, 256, smemFFT>>>(inputs, kern, Xp, Wp);
    pointwise_kernel<<<260, 256, smemPW>>>(Xp, Wp, Zh);
    ifft3d_packed<<<128, 256, smemFFT>>>(Zh, bias, out);
}